// round 5
// baseline (speedup 1.0000x reference)
#include <cuda_runtime.h>
#include <math.h>

#define NN   100000
#define NE   3200000
#define DIN  64
#define DH   40
#define DOUT 24
#define NBLK_SCAN 98                 // ceil(NN / 1024)
#define NE_PAD (NE + 31 * NN + 32)   // padded CSR capacity

typedef unsigned long long ull;

// ---------------- scratch (static device globals; no allocation) -------------
__device__ __align__(16) float g_xl[(NN + 1) * DH];    // row NN = dummy zero row
__device__ __align__(16) float g_s1[NN * DH];
__device__ __align__(16) float g_hl[(NN + 1) * DOUT];  // row NN = dummy zero row
__device__ __align__(16) float g_hr[NN * DOUT];
__device__ int   g_deg[NN];              // zero at load; re-zeroed by scan1 each call
__device__ float g_invdeg[NN];
__device__ int   g_rowptr[NN + 1];       // padded offsets (32-aligned segments)
__device__ int   g_wptr[NN];
__device__ int   g_srcs[NE_PAD];
__device__ int   g_bsum[NBLK_SCAN];

// ---------------- packed f32x2 helpers ----------------------------------------
__device__ __forceinline__ ull fma2(ull a, ull b, ull c) {
    ull d;
    asm("fma.rn.f32x2 %0, %1, %2, %3;" : "=l"(d) : "l"(a), "l"(b), "l"(c));
    return d;
}
__device__ __forceinline__ float hadd2(ull a) {
    float lo, hi;
    asm("mov.b64 {%0,%1}, %2;" : "=f"(lo), "=f"(hi) : "l"(a));
    return lo + hi;
}
__device__ __forceinline__ ull pack2(float lo, float hi) {
    ull r;
    asm("mov.b64 %0, {%1,%2};" : "=l"(r) : "f"(lo), "f"(hi));
    return r;
}

// ---------------- CSR build ----------------------------------------------------
__global__ void k_hist(const int4* __restrict__ dst4) {
    int e = blockIdx.x * blockDim.x + threadIdx.x;
    if (e < NE / 4) {
        int4 d = dst4[e];
        atomicAdd(&g_deg[d.x], 1);
        atomicAdd(&g_deg[d.y], 1);
        atomicAdd(&g_deg[d.z], 1);
        atomicAdd(&g_deg[d.w], 1);
    }
}

// block-local exclusive scan of PADDED degrees (1024/block); also emits invdeg
// and re-zeroes g_deg for the next call.
__global__ __launch_bounds__(256) void k_scan1() {
    __shared__ int warp_sums[8];
    int tid = threadIdx.x;
    int base = blockIdx.x * 1024 + tid * 4;
    int v[4];
#pragma unroll
    for (int q = 0; q < 4; ++q) {
        int idx = base + q;
        int d = 0;
        if (idx < NN) {
            d = g_deg[idx];
            g_deg[idx] = 0;                                  // reset for next call
            g_invdeg[idx] = 1.f / (float)max(d, 1);
        }
        v[q] = (d + 31) & ~31;                               // padded degree
    }
    int s = v[0] + v[1] + v[2] + v[3];
    int lane = tid & 31, wid = tid >> 5;
    int incl = s;
#pragma unroll
    for (int o = 1; o < 32; o <<= 1) {
        int t = __shfl_up_sync(0xffffffffu, incl, o);
        if (lane >= o) incl += t;
    }
    if (lane == 31) warp_sums[wid] = incl;
    __syncthreads();
    if (wid == 0) {
        int ws = (lane < 8) ? warp_sums[lane] : 0;
#pragma unroll
        for (int o = 1; o < 8; o <<= 1) {
            int t = __shfl_up_sync(0xffffffffu, ws, o);
            if (lane >= o) ws += t;
        }
        if (lane < 8) warp_sums[lane] = ws;
    }
    __syncthreads();
    int excl = incl - s + (wid ? warp_sums[wid - 1] : 0);
    int run = excl;
#pragma unroll
    for (int q = 0; q < 4; ++q) {
        int idx = base + q;
        if (idx < NN) g_rowptr[idx] = run;
        run += v[q];
    }
    if (tid == 255) g_bsum[blockIdx.x] = warp_sums[7];
}

// fused cross-block offset + apply: each block sums prior block totals itself.
__global__ __launch_bounds__(256) void k_scan23() {
    __shared__ int soff;
    int tid = threadIdx.x;
    if (tid < 32) {
        int acc = 0;
        for (int b = tid; b < NBLK_SCAN; b += 32)
            if (b < blockIdx.x) acc += g_bsum[b];
#pragma unroll
        for (int o = 16; o >= 1; o >>= 1) acc += __shfl_xor_sync(0xffffffffu, acc, o);
        if (tid == 0) soff = acc;
    }
    __syncthreads();
    int off = soff;
    int base = blockIdx.x * 1024 + tid * 4;
#pragma unroll
    for (int q = 0; q < 4; ++q) {
        int idx = base + q;
        if (idx < NN) {
            int r = g_rowptr[idx] + off;
            g_rowptr[idx] = r;
            g_wptr[idx]   = r;
        }
    }
    if (blockIdx.x == NBLK_SCAN - 1 && tid == 0)
        g_rowptr[NN] = off + g_bsum[NBLK_SCAN - 1];
}

__global__ void k_place(const int4* __restrict__ src4, const int4* __restrict__ dst4) {
    int e = blockIdx.x * blockDim.x + threadIdx.x;
    if (e < NE / 4) {
        int4 s = src4[e];
        int4 d = dst4[e];
        g_srcs[atomicAdd(&g_wptr[d.x], 1)] = s.x;
        g_srcs[atomicAdd(&g_wptr[d.y], 1)] = s.y;
        g_srcs[atomicAdd(&g_wptr[d.z], 1)] = s.z;
        g_srcs[atomicAdd(&g_wptr[d.w], 1)] = s.w;
    }
}

// fill pad slots with dummy node NN (zero rows). one warp per node.
__global__ __launch_bounds__(256) void k_fill() {
    int w = blockIdx.x * 8 + (threadIdx.x >> 5);
    int lane = threadIdx.x & 31;
    if (w >= NN) return;
    int b = g_wptr[w];          // true end after place
    int e = g_rowptr[w + 1];    // padded end
    for (int i = b + lane; i < e; i += 32) g_srcs[i] = NN;
}

// ---------------- xl = x @ W1_l^T  (64 -> 40), thread-per-node -----------------
__global__ __launch_bounds__(256) void k_gemm_xl(const float* __restrict__ x,
                                                 const float* __restrict__ W1l) {
    __shared__ ull sW[DH * DIN / 2];
    int tid = threadIdx.x;
    for (int i = tid; i < DH * DIN / 2; i += 256)
        sW[i] = ((const ull*)W1l)[i];
    __syncthreads();

    int n = blockIdx.x * 256 + tid;
    if (n >= NN) return;

    ull xr[DIN / 2];
    const ulonglong2* xp = (const ulonglong2*)(x + (size_t)n * DIN);
#pragma unroll
    for (int q = 0; q < DIN / 4; ++q) {
        ulonglong2 t = xp[q];
        xr[2 * q] = t.x; xr[2 * q + 1] = t.y;
    }
    float* orow = g_xl + (size_t)n * DH;
    for (int j = 0; j < DH; j += 2) {
        ull a0 = 0ull, a1 = 0ull;
        const ull* w0 = sW + j * (DIN / 2);
        const ull* w1 = w0 + (DIN / 2);
#pragma unroll
        for (int p = 0; p < DIN / 2; ++p) {
            a0 = fma2(xr[p], w0[p], a0);
            a1 = fma2(xr[p], w1[p], a1);
        }
        float2 o; o.x = hadd2(a0); o.y = hadd2(a1);
        *(float2*)(orow + j) = o;
    }
}

// ---------------- agg1: s1[n] = mean over edges of xl[src] ---------------------
// one warp per node; lanes 0-9 own one float4 of the 40-float row; padded rows.
__global__ __launch_bounds__(256) void k_agg1() {
    int w = blockIdx.x * 8 + (threadIdx.x >> 5);
    int lane = threadIdx.x & 31;
    if (w >= NN) return;
    int beg = g_rowptr[w], end = g_rowptr[w + 1];
    const float4* xl4 = (const float4*)g_xl;
    float4 a0 = make_float4(0.f, 0.f, 0.f, 0.f);
    float4 a1 = make_float4(0.f, 0.f, 0.f, 0.f);
    float4 a2 = make_float4(0.f, 0.f, 0.f, 0.f);
    float4 a3 = make_float4(0.f, 0.f, 0.f, 0.f);
    for (int i = beg; i < end; i += 32) {
        int sv = g_srcs[i + lane];
#pragma unroll
        for (int j = 0; j < 32; j += 4) {
            int s0 = __shfl_sync(0xffffffffu, sv, j);
            int s1 = __shfl_sync(0xffffffffu, sv, j + 1);
            int s2 = __shfl_sync(0xffffffffu, sv, j + 2);
            int s3 = __shfl_sync(0xffffffffu, sv, j + 3);
            if (lane < 10) {
                float4 v0 = xl4[(size_t)s0 * 10 + lane];
                float4 v1 = xl4[(size_t)s1 * 10 + lane];
                float4 v2 = xl4[(size_t)s2 * 10 + lane];
                float4 v3 = xl4[(size_t)s3 * 10 + lane];
                a0.x += v0.x; a0.y += v0.y; a0.z += v0.z; a0.w += v0.w;
                a1.x += v1.x; a1.y += v1.y; a1.z += v1.z; a1.w += v1.w;
                a2.x += v2.x; a2.y += v2.y; a2.z += v2.z; a2.w += v2.w;
                a3.x += v3.x; a3.y += v3.y; a3.z += v3.z; a3.w += v3.w;
            }
        }
    }
    if (lane < 10) {
        float inv = g_invdeg[w];
        float4 r;
        r.x = (a0.x + a1.x + a2.x + a3.x) * inv;
        r.y = (a0.y + a1.y + a2.y + a3.y) * inv;
        r.z = (a0.z + a1.z + a2.z + a3.z) * inv;
        r.w = (a0.w + a1.w + a2.w + a3.w) * inv;
        ((float4*)g_s1)[(size_t)w * 10 + lane] = r;
    }
}

// ---------------- fused: h = relu(s1 + b1 + x@W1r^T); hl = h@W2l^T; hr = h@W2r^T + b2
__global__ __launch_bounds__(256) void k_fused(const float* __restrict__ x,
                                               const float* __restrict__ W1r,
                                               const float* __restrict__ b1,
                                               const float* __restrict__ W2l,
                                               const float* __restrict__ W2r,
                                               const float* __restrict__ b2) {
    __shared__ ull sW1[DH * DIN / 2];
    __shared__ ull sWl[DOUT * DH / 2];
    __shared__ ull sWr[DOUT * DH / 2];
    __shared__ float sb1[DH];
    __shared__ float sb2[DOUT];
    int tid = threadIdx.x;
    for (int i = tid; i < DH * DIN / 2; i += 256)
        sW1[i] = ((const ull*)W1r)[i];
    for (int i = tid; i < DOUT * DH / 2; i += 256) {
        sWl[i] = ((const ull*)W2l)[i];
        sWr[i] = ((const ull*)W2r)[i];
    }
    if (tid < DH)   sb1[tid] = b1[tid];
    if (tid < DOUT) sb2[tid] = b2[tid];
    __syncthreads();

    int n = blockIdx.x * 256 + tid;
    if (n >= NN) return;

    ull xr[DIN / 2];
    const ulonglong2* xp = (const ulonglong2*)(x + (size_t)n * DIN);
#pragma unroll
    for (int q = 0; q < DIN / 4; ++q) {
        ulonglong2 t = xp[q];
        xr[2 * q] = t.x; xr[2 * q + 1] = t.y;
    }

    ull h2[DH / 2];
    const float2* s1p = (const float2*)(g_s1 + (size_t)n * DH);
    for (int j = 0; j < DH; j += 2) {
        ull a0 = 0ull, a1 = 0ull;
        const ull* w0 = sW1 + j * (DIN / 2);
        const ull* w1 = w0 + (DIN / 2);
#pragma unroll
        for (int p = 0; p < DIN / 2; ++p) {
            a0 = fma2(xr[p], w0[p], a0);
            a1 = fma2(xr[p], w1[p], a1);
        }
        float2 sres = s1p[j / 2];
        float r0 = hadd2(a0) + sres.x + sb1[j];
        float r1 = hadd2(a1) + sres.y + sb1[j + 1];
        h2[j / 2] = pack2(fmaxf(r0, 0.f), fmaxf(r1, 0.f));
    }

    float* ol  = g_hl + (size_t)n * DOUT;
    float* orr = g_hr + (size_t)n * DOUT;
    for (int j = 0; j < DOUT; j += 2) {
        ull al0 = 0ull, al1 = 0ull, ar0 = 0ull, ar1 = 0ull;
        const ull* wl0 = sWl + j * (DH / 2);
        const ull* wl1 = wl0 + (DH / 2);
        const ull* wr0 = sWr + j * (DH / 2);
        const ull* wr1 = wr0 + (DH / 2);
#pragma unroll
        for (int p = 0; p < DH / 2; ++p) {
            al0 = fma2(h2[p], wl0[p], al0);
            al1 = fma2(h2[p], wl1[p], al1);
            ar0 = fma2(h2[p], wr0[p], ar0);
            ar1 = fma2(h2[p], wr1[p], ar1);
        }
        float2 vl; vl.x = hadd2(al0); vl.y = hadd2(al1);
        float2 vr; vr.x = hadd2(ar0) + sb2[j]; vr.y = hadd2(ar1) + sb2[j + 1];
        *(float2*)(ol + j)  = vl;
        *(float2*)(orr + j) = vr;
    }
}

// ---------------- agg2 + log_softmax fused --------------------------------------
// one warp per node; lanes 0-5 own one float4 of the 24-float row; padded rows.
__global__ __launch_bounds__(256) void k_agg2_final(float* __restrict__ out) {
    int w = blockIdx.x * 8 + (threadIdx.x >> 5);
    int lane = threadIdx.x & 31;
    if (w >= NN) return;
    int beg = g_rowptr[w], end = g_rowptr[w + 1];
    const float4* hl4 = (const float4*)g_hl;
    float4 a0 = make_float4(0.f, 0.f, 0.f, 0.f);
    float4 a1 = make_float4(0.f, 0.f, 0.f, 0.f);
    float4 a2 = make_float4(0.f, 0.f, 0.f, 0.f);
    float4 a3 = make_float4(0.f, 0.f, 0.f, 0.f);
    for (int i = beg; i < end; i += 32) {
        int sv = g_srcs[i + lane];
#pragma unroll
        for (int j = 0; j < 32; j += 4) {
            int s0 = __shfl_sync(0xffffffffu, sv, j);
            int s1 = __shfl_sync(0xffffffffu, sv, j + 1);
            int s2 = __shfl_sync(0xffffffffu, sv, j + 2);
            int s3 = __shfl_sync(0xffffffffu, sv, j + 3);
            if (lane < 6) {
                float4 v0 = hl4[(size_t)s0 * 6 + lane];
                float4 v1 = hl4[(size_t)s1 * 6 + lane];
                float4 v2 = hl4[(size_t)s2 * 6 + lane];
                float4 v3 = hl4[(size_t)s3 * 6 + lane];
                a0.x += v0.x; a0.y += v0.y; a0.z += v0.z; a0.w += v0.w;
                a1.x += v1.x; a1.y += v1.y; a1.z += v1.z; a1.w += v1.w;
                a2.x += v2.x; a2.y += v2.y; a2.z += v2.z; a2.w += v2.w;
                a3.x += v3.x; a3.y += v3.y; a3.z += v3.z; a3.w += v3.w;
            }
        }
    }
    float inv = g_invdeg[w];
    float4 t = make_float4(0.f, 0.f, 0.f, 0.f);
    if (lane < 6) {
        float4 r = ((const float4*)g_hr)[(size_t)w * 6 + lane];
        t.x = (a0.x + a1.x + a2.x + a3.x) * inv + r.x;
        t.y = (a0.y + a1.y + a2.y + a3.y) * inv + r.y;
        t.z = (a0.z + a1.z + a2.z + a3.z) * inv + r.z;
        t.w = (a0.w + a1.w + a2.w + a3.w) * inv + r.w;
    }
    float m = (lane < 6) ? fmaxf(fmaxf(t.x, t.y), fmaxf(t.z, t.w)) : -INFINITY;
#pragma unroll
    for (int o = 16; o >= 1; o >>= 1) m = fmaxf(m, __shfl_xor_sync(0xffffffffu, m, o));
    float e = 0.f;
    if (lane < 6)
        e = expf(t.x - m) + expf(t.y - m) + expf(t.z - m) + expf(t.w - m);
#pragma unroll
    for (int o = 16; o >= 1; o >>= 1) e += __shfl_xor_sync(0xffffffffu, e, o);
    float l = m + logf(e);
    if (lane < 6) {
        float4 r;
        r.x = t.x - l; r.y = t.y - l; r.z = t.z - l; r.w = t.w - l;
        ((float4*)out)[(size_t)w * 6 + lane] = r;
    }
}

// ---------------- launch ---------------------------------------------------------
extern "C" void kernel_launch(void* const* d_in, const int* in_sizes, int n_in,
                              void* d_out, int out_size) {
    const float* x   = (const float*)d_in[0];
    const int*   ei  = (const int*)  d_in[1];
    const float* W1l = (const float*)d_in[2];
    const float* b1  = (const float*)d_in[3];
    const float* W1r = (const float*)d_in[4];
    const float* W2l = (const float*)d_in[5];
    const float* b2  = (const float*)d_in[6];
    const float* W2r = (const float*)d_in[7];
    float* out = (float*)d_out;

    const int4* src4 = (const int4*)ei;
    const int4* dst4 = (const int4*)(ei + NE);

    const int nblk_node  = (NN + 255) / 256;       // 391
    const int nblk_edge4 = (NE / 4 + 255) / 256;   // 3125
    const int nblk_warp  = (NN + 7) / 8;           // 12500

    // CSR build (g_deg is zero at module load and re-zeroed by k_scan1 each call)
    k_hist<<<nblk_edge4, 256>>>(dst4);             // launch 0
    k_scan1<<<NBLK_SCAN, 256>>>();                 // launch 1
    k_scan23<<<NBLK_SCAN, 256>>>();                // launch 2
    k_place<<<nblk_edge4, 256>>>(src4, dst4);      // launch 3  (ncu capture slot)
    k_fill<<<nblk_warp, 256>>>();                  // launch 4

    // layer 1
    k_gemm_xl<<<nblk_node, 256>>>(x, W1l);
    k_agg1<<<nblk_warp, 256>>>();

    // layer-1 right GEMM + layer-2 GEMMs fused
    k_fused<<<nblk_node, 256>>>(x, W1r, b1, W2l, W2r, b2);

    // layer-2 aggregation + log_softmax
    k_agg2_final<<<nblk_warp, 256>>>(out);
}

// round 6
// speedup vs baseline: 1.3025x; 1.3025x over previous
#include <cuda_runtime.h>
#include <math.h>

#define NN   100000
#define NE   3200000
#define DIN  64
#define DH   40
#define DOUT 24

typedef unsigned long long ull;

// ---------------- scratch (static device globals; no allocation) -------------
__device__ __align__(16) float g_xl[NN * DH];    // x @ W1_l^T
__device__ __align__(16) float g_s1[NN * DH];    // scatter sum layer 1
__device__ __align__(16) float g_hl[NN * DOUT];  // h @ W2_l^T
__device__ __align__(16) float g_hr[NN * DOUT];  // h @ W2_r^T + b2
__device__ __align__(16) float g_s2[NN * DOUT];  // scatter sum layer 2
__device__ float g_cnt[NN];                      // in-degree

// ---------------- packed f32x2 helpers ----------------------------------------
__device__ __forceinline__ ull fma2(ull a, ull b, ull c) {
    ull d;
    asm("fma.rn.f32x2 %0, %1, %2, %3;" : "=l"(d) : "l"(a), "l"(b), "l"(c));
    return d;
}
__device__ __forceinline__ float hadd2(ull a) {
    float lo, hi;
    asm("mov.b64 {%0,%1}, %2;" : "=f"(lo), "=f"(hi) : "l"(a));
    return lo + hi;
}
__device__ __forceinline__ ull pack2(float lo, float hi) {
    ull r;
    asm("mov.b64 %0, {%1,%2};" : "=l"(r) : "f"(lo), "f"(hi));
    return r;
}

// ---------------- zero kernels (split so scatter1 lands at launch idx 3) ------
__global__ void k_zero1() {   // s1 + cnt
    int t = blockIdx.x * blockDim.x + threadIdx.x;
    int stride = gridDim.x * blockDim.x;
    float4* s14 = (float4*)g_s1;
    for (int i = t; i < NN * DH / 4; i += stride) s14[i] = make_float4(0.f,0.f,0.f,0.f);
    for (int i = t; i < NN; i += stride) g_cnt[i] = 0.f;
}
__global__ void k_zero2() {   // s2
    int t = blockIdx.x * blockDim.x + threadIdx.x;
    int stride = gridDim.x * blockDim.x;
    float4* s24 = (float4*)g_s2;
    for (int i = t; i < NN * DOUT / 4; i += stride) s24[i] = make_float4(0.f,0.f,0.f,0.f);
}

// ---------------- xl = x @ W1_l^T  (64 -> 40), thread-per-node -----------------
__global__ __launch_bounds__(256) void k_gemm_xl(const float* __restrict__ x,
                                                 const float* __restrict__ W1l) {
    __shared__ ull sW[DH * DIN / 2];
    int tid = threadIdx.x;
    for (int i = tid; i < DH * DIN / 2; i += 256)
        sW[i] = ((const ull*)W1l)[i];
    __syncthreads();

    int n = blockIdx.x * 256 + tid;
    if (n >= NN) return;

    ull xr[DIN / 2];
    const ulonglong2* xp = (const ulonglong2*)(x + (size_t)n * DIN);
#pragma unroll
    for (int q = 0; q < DIN / 4; ++q) {
        ulonglong2 t = xp[q];
        xr[2 * q] = t.x; xr[2 * q + 1] = t.y;
    }
    float* orow = g_xl + (size_t)n * DH;
    for (int j = 0; j < DH; j += 2) {
        ull a0 = 0ull, a1 = 0ull;
        const ull* w0 = sW + j * (DIN / 2);
        const ull* w1 = w0 + (DIN / 2);
#pragma unroll
        for (int p = 0; p < DIN / 2; ++p) {
            a0 = fma2(xr[p], w0[p], a0);
            a1 = fma2(xr[p], w1[p], a1);
        }
        float2 o; o.x = hadd2(a0); o.y = hadd2(a1);
        *(float2*)(orow + j) = o;
    }
}

// ---------------- scatter layer 1: s1[dst] += xl[src], cnt[dst] += 1 -----------
// 10 threads per edge, one float4 each (row = 160B contiguous)
__global__ void k_scatter1(const int* __restrict__ src, const int* __restrict__ dst) {
    unsigned t = blockIdx.x * blockDim.x + threadIdx.x;
    if (t >= (unsigned)NE * 10u) return;
    unsigned e = t / 10u, c = t - e * 10u;
    int s = src[e], d = dst[e];
    float4 v = ((const float4*)g_xl)[(size_t)s * 10 + c];
    float* p = &g_s1[(size_t)d * DH + c * 4];
    asm volatile("red.global.add.v4.f32 [%0], {%1,%2,%3,%4};"
                 :: "l"(p), "f"(v.x), "f"(v.y), "f"(v.z), "f"(v.w) : "memory");
    if (c == 0) {
        float* q = &g_cnt[d];
        asm volatile("red.global.add.f32 [%0], %1;" :: "l"(q), "f"(1.0f) : "memory");
    }
}

// ---------------- fused: h = relu(s1/cnt + b1 + x@W1r^T); hl = h@W2l^T; hr = h@W2r^T + b2
__global__ __launch_bounds__(256) void k_fused(const float* __restrict__ x,
                                               const float* __restrict__ W1r,
                                               const float* __restrict__ b1,
                                               const float* __restrict__ W2l,
                                               const float* __restrict__ W2r,
                                               const float* __restrict__ b2) {
    __shared__ ull sW1[DH * DIN / 2];
    __shared__ ull sWl[DOUT * DH / 2];
    __shared__ ull sWr[DOUT * DH / 2];
    __shared__ float sb1[DH];
    __shared__ float sb2[DOUT];
    int tid = threadIdx.x;
    for (int i = tid; i < DH * DIN / 2; i += 256)
        sW1[i] = ((const ull*)W1r)[i];
    for (int i = tid; i < DOUT * DH / 2; i += 256) {
        sWl[i] = ((const ull*)W2l)[i];
        sWr[i] = ((const ull*)W2r)[i];
    }
    if (tid < DH)   sb1[tid] = b1[tid];
    if (tid < DOUT) sb2[tid] = b2[tid];
    __syncthreads();

    int n = blockIdx.x * 256 + tid;
    if (n >= NN) return;

    ull xr[DIN / 2];
    const ulonglong2* xp = (const ulonglong2*)(x + (size_t)n * DIN);
#pragma unroll
    for (int q = 0; q < DIN / 4; ++q) {
        ulonglong2 t = xp[q];
        xr[2 * q] = t.x; xr[2 * q + 1] = t.y;
    }

    float inv = __fdividef(1.f, fmaxf(g_cnt[n], 1.f));

    ull h2[DH / 2];
    const float2* s1p = (const float2*)(g_s1 + (size_t)n * DH);
    for (int j = 0; j < DH; j += 2) {
        ull a0 = 0ull, a1 = 0ull;
        const ull* w0 = sW1 + j * (DIN / 2);
        const ull* w1 = w0 + (DIN / 2);
#pragma unroll
        for (int p = 0; p < DIN / 2; ++p) {
            a0 = fma2(xr[p], w0[p], a0);
            a1 = fma2(xr[p], w1[p], a1);
        }
        float2 sres = s1p[j / 2];
        float r0 = hadd2(a0) + sres.x * inv + sb1[j];
        float r1 = hadd2(a1) + sres.y * inv + sb1[j + 1];
        h2[j / 2] = pack2(fmaxf(r0, 0.f), fmaxf(r1, 0.f));
    }

    float* ol  = g_hl + (size_t)n * DOUT;
    float* orr = g_hr + (size_t)n * DOUT;
    for (int j = 0; j < DOUT; j += 2) {
        ull al0 = 0ull, al1 = 0ull, ar0 = 0ull, ar1 = 0ull;
        const ull* wl0 = sWl + j * (DH / 2);
        const ull* wl1 = wl0 + (DH / 2);
        const ull* wr0 = sWr + j * (DH / 2);
        const ull* wr1 = wr0 + (DH / 2);
#pragma unroll
        for (int p = 0; p < DH / 2; ++p) {
            al0 = fma2(h2[p], wl0[p], al0);
            al1 = fma2(h2[p], wl1[p], al1);
            ar0 = fma2(h2[p], wr0[p], ar0);
            ar1 = fma2(h2[p], wr1[p], ar1);
        }
        float2 vl; vl.x = hadd2(al0); vl.y = hadd2(al1);
        float2 vr; vr.x = hadd2(ar0) + sb2[j]; vr.y = hadd2(ar1) + sb2[j + 1];
        *(float2*)(ol + j)  = vl;
        *(float2*)(orr + j) = vr;
    }
}

// ---------------- scatter layer 2: s2[dst] += hl[src] ---------------------------
// 6 threads per edge, one float4 each (row = 96B contiguous)
__global__ void k_scatter2(const int* __restrict__ src, const int* __restrict__ dst) {
    unsigned t = blockIdx.x * blockDim.x + threadIdx.x;
    if (t >= (unsigned)NE * 6u) return;
    unsigned e = t / 6u, c = t - e * 6u;
    int s = src[e], d = dst[e];
    float4 v = ((const float4*)g_hl)[(size_t)s * 6 + c];
    float* p = &g_s2[(size_t)d * DOUT + c * 4];
    asm volatile("red.global.add.v4.f32 [%0], {%1,%2,%3,%4};"
                 :: "l"(p), "f"(v.x), "f"(v.y), "f"(v.z), "f"(v.w) : "memory");
}

// ---------------- out = log_softmax(s2/cnt + hr), thread-per-node ---------------
__global__ void k_final(float* __restrict__ out) {
    int n = blockIdx.x * blockDim.x + threadIdx.x;
    if (n >= NN) return;
    float inv = __fdividef(1.f, fmaxf(g_cnt[n], 1.f));
    const float4* s24 = (const float4*)g_s2;
    const float4* hr4 = (const float4*)g_hr;
    float v[DOUT];
#pragma unroll
    for (int kk = 0; kk < 6; ++kk) {
        float4 a = s24[(size_t)n * 6 + kk];
        float4 b = hr4[(size_t)n * 6 + kk];
        v[kk * 4 + 0] = a.x * inv + b.x;
        v[kk * 4 + 1] = a.y * inv + b.y;
        v[kk * 4 + 2] = a.z * inv + b.z;
        v[kk * 4 + 3] = a.w * inv + b.w;
    }
    float m = v[0];
#pragma unroll
    for (int j = 1; j < DOUT; ++j) m = fmaxf(m, v[j]);
    float s = 0.f;
#pragma unroll
    for (int j = 0; j < DOUT; ++j) s += expf(v[j] - m);
    float l = m + logf(s);
    float4* o4 = (float4*)out;
#pragma unroll
    for (int kk = 0; kk < 6; ++kk) {
        float4 r;
        r.x = v[kk * 4 + 0] - l;
        r.y = v[kk * 4 + 1] - l;
        r.z = v[kk * 4 + 2] - l;
        r.w = v[kk * 4 + 3] - l;
        o4[(size_t)n * 6 + kk] = r;
    }
}

// ---------------- launch ----------------------------------------------------------
extern "C" void kernel_launch(void* const* d_in, const int* in_sizes, int n_in,
                              void* d_out, int out_size) {
    const float* x   = (const float*)d_in[0];
    const int*   ei  = (const int*)  d_in[1];
    const float* W1l = (const float*)d_in[2];
    const float* b1  = (const float*)d_in[3];
    const float* W1r = (const float*)d_in[4];
    const float* W2l = (const float*)d_in[5];
    const float* b2  = (const float*)d_in[6];
    const float* W2r = (const float*)d_in[7];
    float* out = (float*)d_out;

    const int* src = ei;
    const int* dst = ei + NE;

    const int nblk_node = (NN + 255) / 256;   // 391

    k_zero1<<<2048, 256>>>();                                        // launch 0
    k_zero2<<<1024, 256>>>();                                        // launch 1
    k_gemm_xl<<<nblk_node, 256>>>(x, W1l);                           // launch 2
    {
        unsigned T = (unsigned)NE * 10u;
        k_scatter1<<<(T + 255) / 256, 256>>>(src, dst);              // launch 3 (ncu slot)
    }
    k_fused<<<nblk_node, 256>>>(x, W1r, b1, W2l, W2r, b2);           // launch 4
    {
        unsigned T = (unsigned)NE * 6u;
        k_scatter2<<<(T + 255) / 256, 256>>>(src, dst);              // launch 5
    }
    k_final<<<(NN + 255) / 256, 256>>>(out);                         // launch 6
}